// round 6
// baseline (speedup 1.0000x reference)
#include <cuda_runtime.h>
#include <cstdint>

// Problem constants
#define N_PIX 4194304      // 4*4*512*512
#define NQ    1048576      // N_PIX / 4  (float4 groups)
#define NB    101          // bins / categories
#define RSTR  104          // padded cdf row stride (floats)
#define NBK   256          // u-quantile buckets per row

// smem layout (dynamic): [ cdf: NB*RSTR floats ][ tbl: NB*NBK u16 ]
#define CDF_BYTES  (NB * RSTR * 4)            // 42016
#define TBL_BYTES  (NB * NBK * 2)             // 51712
#define SMEM_TOTAL (CDF_BYTES + TBL_BYTES)    // 93728

// ---------------------------------------------------------------------------
// JAX *partitionable* threefry bits for 32-bit draws, key = jax.random.key(1):
//   (k1,k2) = (0,1);  ks0=0, ks1=1, ks2 = 0^1^0x1BD11BDA = 0x1BD11BDB
//   per element i (size < 2^32): counts_hi = 0, counts_lo = i
//   (y0,y1) = threefry2x32((0,1), (0,i));  bits = y0 ^ y1
// ---------------------------------------------------------------------------
__device__ __forceinline__ uint32_t threefry_bits(uint32_t i) {
    const uint32_t ks0 = 0u;
    const uint32_t ks1 = 1u;
    const uint32_t ks2 = 0x1BD11BDBu;

    uint32_t x0 = 0u + ks0;
    uint32_t x1 = i  + ks1;

#define TF_ROUND(r) do { x0 += x1; x1 = __funnelshift_l(x1, x1, (r)); x1 ^= x0; } while (0)

    TF_ROUND(13); TF_ROUND(15); TF_ROUND(26); TF_ROUND(6);
    x0 += ks1; x1 += ks2 + 1u;
    TF_ROUND(17); TF_ROUND(29); TF_ROUND(16); TF_ROUND(24);
    x0 += ks2; x1 += ks0 + 2u;
    TF_ROUND(13); TF_ROUND(15); TF_ROUND(26); TF_ROUND(6);
    x0 += ks0; x1 += ks1 + 3u;
    TF_ROUND(17); TF_ROUND(29); TF_ROUND(16); TF_ROUND(24);
    x0 += ks1; x1 += ks2 + 4u;
    TF_ROUND(13); TF_ROUND(15); TF_ROUND(26); TF_ROUND(6);
    x0 += ks2; x1 += ks0 + 5u;

#undef TF_ROUND
    return x0 ^ x1;           // partitionable 32-bit combine
}

// digitize(x, arange(0,0.5,0.005)) = # of float32 edges e(j)=j*0.005f with e<=x
__device__ __forceinline__ int refl_bin(float xv) {
    int r = (int)(xv * 200.0f) + 1;
    r = min(r, 100);
    if (r < 100 && (float)r * 0.005f <= xv) ++r;
    if ((float)(r - 1) * 0.005f > xv) --r;
    return r;   // in [0, 100]
}

// searchsorted(cdf_row, u, 'left') via 256-bucket (lo,span) table.
// Row is nondecreasing, so counting (< u) over the first min(span,3) entries
// gives the exact offset; rare span>3 tail handled by a loop.
__device__ __forceinline__ int sample_idx(const float* __restrict__ cdf,
                                          const uint16_t* __restrict__ tbl,
                                          int r, float u) {
    int k = (int)(u * 256.0f);               // exact (power-of-two scale), 0..255

    uint32_t e  = tbl[r * NBK + k];
    int lo   = (int)(e & 0xFFu);
    int span = (int)(e >> 8);

    const float* row = cdf + r * RSTR;
    // lo <= 101; pads row[101..103] = 2.0f keep these loads in-bounds & never < u
    int c = ((span > 0) & (row[lo    ] < u))
          + ((span > 1) & (row[lo + 1] < u))
          + ((span > 2) & (row[lo + 2] < u));
    int j = lo + c;

    if (span > 3 && c == 3) {                // very rare
        j = lo + 3;
        int hi = lo + span;
        while (j < hi && row[j] < u) ++j;
    }
    return min(j, NB - 1);
}

__global__ __launch_bounds__(1024, 2)
void noise_model_kernel(const float4* __restrict__ x4,
                        const float*  __restrict__ nm,
                        float4* __restrict__ out4) {
    extern __shared__ __align__(16) unsigned char smem_raw[];
    float*    cdf = (float*)smem_raw;                  // NB*RSTR
    uint16_t* tbl = (uint16_t*)(smem_raw + CDF_BYTES); // NB*NBK

    const int tid = threadIdx.x;

    // Per-block build: thread t handles row t (cumsum, pads, bucket table).
    if (tid < NB) {
        const float* rowp = nm + tid * NB;
        float*       crow = cdf + tid * RSTR;
        float s = 0.0f;
#pragma unroll 4
        for (int j = 0; j < NB; ++j) {
            s += rowp[j];
            crow[j] = s;
        }
        crow[101] = 2.0f; crow[102] = 2.0f; crow[103] = 2.0f;  // pads

        // two-pointer: lo_k = first j with crow[j] >= k/256 (lo_0 = 0)
        uint16_t* trow = tbl + tid * NBK;
        int lo = 0;
#pragma unroll 1
        for (int k = 0; k < NBK; ++k) {
            float t1 = (float)(k + 1) * 0.00390625f;   // (k+1)/256, exact
            int hi = lo;
            while (hi < NB && crow[hi] < t1) ++hi;     // lo_{k+1}
            trow[k] = (uint16_t)(lo | ((hi - lo) << 8));
            lo = hi;
        }
    }
    __syncthreads();

    const int stride = blockDim.x * gridDim.x;
    for (int g = blockIdx.x * blockDim.x + tid; g < NQ; g += stride) {
        const uint32_t base = (uint32_t)g * 4u;

        // 4 independent threefry evaluations (ILP)
        uint32_t b0 = threefry_bits(base + 0u);
        uint32_t b1 = threefry_bits(base + 1u);
        uint32_t b2 = threefry_bits(base + 2u);
        uint32_t b3 = threefry_bits(base + 3u);

        float u0 = __uint_as_float((b0 >> 9) | 0x3f800000u) - 1.0f;
        float u1 = __uint_as_float((b1 >> 9) | 0x3f800000u) - 1.0f;
        float u2 = __uint_as_float((b2 >> 9) | 0x3f800000u) - 1.0f;
        float u3 = __uint_as_float((b3 >> 9) | 0x3f800000u) - 1.0f;

        float4 xv = x4[g];

        int i0 = sample_idx(cdf, tbl, refl_bin(xv.x), u0);
        int i1 = sample_idx(cdf, tbl, refl_bin(xv.y), u1);
        int i2 = sample_idx(cdf, tbl, refl_bin(xv.z), u2);
        int i3 = sample_idx(cdf, tbl, refl_bin(xv.w), u3);

        float4 o;
        o.x = -0.0101f + 0.0002f * (float)i0;
        o.y = -0.0101f + 0.0002f * (float)i1;
        o.z = -0.0101f + 0.0002f * (float)i2;
        o.w = -0.0101f + 0.0002f * (float)i3;
        out4[g] = o;
    }
}

extern "C" void kernel_launch(void* const* d_in, const int* in_sizes, int n_in,
                              void* d_out, int out_size) {
    // Disambiguate inputs by size: x has 4194304 elems, noise_matrix has 10201.
    const float* a = (const float*)d_in[0];
    const float* b = (const float*)d_in[1];
    const float* x  = a;
    const float* nm = b;
    if (n_in >= 2 && in_sizes[0] < in_sizes[1]) { x = b; nm = a; }
    float* out = (float*)d_out;
    (void)out_size;

    // Opt in to >48KB dynamic smem (93,728 B; 2 CTAs/SM = 187 KB < 227 KB).
    static bool configured = false;
    if (!configured) {
        cudaFuncSetAttribute(noise_model_kernel,
                             cudaFuncAttributeMaxDynamicSharedMemorySize,
                             SMEM_TOTAL);
        configured = true;
    }

    noise_model_kernel<<<296, 1024, SMEM_TOTAL>>>((const float4*)x, nm, (float4*)out);
}

// round 9
// speedup vs baseline: 2.5327x; 2.5327x over previous
#include <cuda_runtime.h>
#include <cstdint>

// Problem constants
#define N_PIX 4194304      // 4*4*512*512
#define NQ    1048576      // N_PIX / 4  (float4 groups)
#define NB    101          // bins / categories
#define RSTR  116          // padded cdf row stride: 101 data + 15 pads
#define NBK   64           // u-quantile buckets per row

// smem layout (dynamic): [ cdf: NB*RSTR floats ][ lut: NB*NBK u8 ]
#define CDF_BYTES  (NB * RSTR * 4)            // 46,864
#define LUT_BYTES  (NB * NBK)                 //  6,464
#define SMEM_TOTAL (CDF_BYTES + LUT_BYTES)    // 53,328

// ---------------------------------------------------------------------------
// JAX *partitionable* threefry bits for 32-bit draws, key = jax.random.key(1):
//   (k1,k2) = (0,1);  ks0=0, ks1=1, ks2 = 0^1^0x1BD11BDA = 0x1BD11BDB
//   per element i (size < 2^32): counts_hi = 0, counts_lo = i
//   (y0,y1) = threefry2x32((0,1), (0,i));  bits = y0 ^ y1
// ---------------------------------------------------------------------------
__device__ __forceinline__ uint32_t threefry_bits(uint32_t i) {
    const uint32_t ks0 = 0u;
    const uint32_t ks1 = 1u;
    const uint32_t ks2 = 0x1BD11BDBu;

    uint32_t x0 = 0u + ks0;
    uint32_t x1 = i  + ks1;

#define TF_ROUND(r) do { x0 += x1; x1 = __funnelshift_l(x1, x1, (r)); x1 ^= x0; } while (0)

    TF_ROUND(13); TF_ROUND(15); TF_ROUND(26); TF_ROUND(6);
    x0 += ks1; x1 += ks2 + 1u;
    TF_ROUND(17); TF_ROUND(29); TF_ROUND(16); TF_ROUND(24);
    x0 += ks2; x1 += ks0 + 2u;
    TF_ROUND(13); TF_ROUND(15); TF_ROUND(26); TF_ROUND(6);
    x0 += ks0; x1 += ks1 + 3u;
    TF_ROUND(17); TF_ROUND(29); TF_ROUND(16); TF_ROUND(24);
    x0 += ks1; x1 += ks2 + 4u;
    TF_ROUND(13); TF_ROUND(15); TF_ROUND(26); TF_ROUND(6);
    x0 += ks2; x1 += ks0 + 5u;

#undef TF_ROUND
    return x0 ^ x1;           // partitionable 32-bit combine
}

// digitize(x, arange(0,0.5,0.005)) = # of float32 edges e(j)=j*0.005f with e<=x
__device__ __forceinline__ int refl_bin(float xv) {
    int r = (int)(xv * 200.0f) + 1;
    r = min(r, 100);
    if (r < 100 && (float)r * 0.005f <= xv) ++r;
    if ((float)(r - 1) * 0.005f > xv) --r;
    return r;   // in [0, 100]
}

// Branchless lower_bound over the 101 real entries of a padded row (build only).
// 7 steps: 2^7 = 128 >= 102 states.
__device__ __forceinline__ int lb101(const float* __restrict__ row, float u) {
    int lo = 0, len = NB;
#pragma unroll
    for (int it = 0; it < 7; ++it) {
        int half = len >> 1;
        int mid  = lo + half;
        bool go  = row[mid] < u;
        lo  = go ? (mid + 1)        : lo;
        len = go ? (len - half - 1) : half;
    }
    return lo;
}

// Branchless lower_bound over the fixed window [lo, lo+15] (hot path).
// 16 states, exactly 4 steps (2^4 = 16). Pads (2.0f) at row[101..115] keep all
// probes in-bounds and never < u, so lo+15 <= 115 is always safe.
__device__ __forceinline__ int lb_win15(const float* __restrict__ row,
                                        int lo, float u) {
    int len = 15;                  // 15 -> 7 -> 3 -> 1 -> 0
#pragma unroll
    for (int it = 0; it < 4; ++it) {
        int half = len >> 1;
        int mid  = lo + half;
        bool go  = row[mid] < u;
        lo  = go ? (mid + 1)        : lo;
        len = go ? (len - half - 1) : half;
    }
    return lo;
}

// searchsorted(cdf_row, u, 'left'), clipped to [0, 100].
// Exact while every bucket span (lut[k+1]-lut[k]) <= 15; for softmax rows the
// violation probability is ~1e-22 per bucket (needs 15 consecutive probs < 1e-3).
__device__ __forceinline__ int sample_idx(const float* __restrict__ cdf,
                                          const uint8_t* __restrict__ lut,
                                          int r, float u) {
    int k  = (int)(u * 64.0f);                 // exact (power-of-two scale)
    int lo = lut[r * NBK + k];                 // lower_bound(row, k/64) <= answer
    int j  = lb_win15(cdf + r * RSTR, lo, u);
    return min(j, NB - 1);
}

__global__ __launch_bounds__(1024, 2)
void noise_model_kernel(const float4* __restrict__ x4,
                        const float*  __restrict__ nm,
                        float4* __restrict__ out4) {
    extern __shared__ __align__(16) unsigned char smem_raw[];
    float*   cdf = (float*)smem_raw;                 // NB * RSTR
    uint8_t* lut = (uint8_t*)(smem_raw + CDF_BYTES); // NB * NBK

    const int tid = threadIdx.x;

    // Build 1: thread t = cumsum of row t (left-to-right, matches XLA) + pads.
    if (tid < NB) {
        const float* rowp = nm + tid * NB;
        float*       crow = cdf + tid * RSTR;
        float s = 0.0f;
#pragma unroll 4
        for (int j = 0; j < NB; ++j) {
            s += rowp[j];
            crow[j] = s;
        }
#pragma unroll
        for (int j = NB; j < RSTR; ++j) crow[j] = 2.0f;  // pads, never < u
    }
    __syncthreads();

    // Build 2: all threads fill the bucket LUT (6464 entries, ~6/thread).
    for (int e = tid; e < NB * NBK; e += 1024) {
        int   r = e >> 6;                  // e / NBK
        int   k = e & (NBK - 1);
        float t = (float)k * 0.015625f;    // k/64, exact
        int  lo = lb101(cdf + r * RSTR, t);
        lut[e] = (uint8_t)min(lo, NB - 1);
    }
    __syncthreads();

    const int stride = blockDim.x * gridDim.x;
#pragma unroll 1
    for (int g = blockIdx.x * blockDim.x + tid; g < NQ; g += stride) {
        const uint32_t base = (uint32_t)g * 4u;

        // 4 independent threefry evaluations (ILP)
        uint32_t b0 = threefry_bits(base + 0u);
        uint32_t b1 = threefry_bits(base + 1u);
        uint32_t b2 = threefry_bits(base + 2u);
        uint32_t b3 = threefry_bits(base + 3u);

        float u0 = __uint_as_float((b0 >> 9) | 0x3f800000u) - 1.0f;
        float u1 = __uint_as_float((b1 >> 9) | 0x3f800000u) - 1.0f;
        float u2 = __uint_as_float((b2 >> 9) | 0x3f800000u) - 1.0f;
        float u3 = __uint_as_float((b3 >> 9) | 0x3f800000u) - 1.0f;

        float4 xv = x4[g];

        int i0 = sample_idx(cdf, lut, refl_bin(xv.x), u0);
        int i1 = sample_idx(cdf, lut, refl_bin(xv.y), u1);
        int i2 = sample_idx(cdf, lut, refl_bin(xv.z), u2);
        int i3 = sample_idx(cdf, lut, refl_bin(xv.w), u3);

        float4 o;
        o.x = -0.0101f + 0.0002f * (float)i0;
        o.y = -0.0101f + 0.0002f * (float)i1;
        o.z = -0.0101f + 0.0002f * (float)i2;
        o.w = -0.0101f + 0.0002f * (float)i3;
        out4[g] = o;
    }
}

extern "C" void kernel_launch(void* const* d_in, const int* in_sizes, int n_in,
                              void* d_out, int out_size) {
    // Disambiguate inputs by size: x has 4194304 elems, noise_matrix has 10201.
    const float* a = (const float*)d_in[0];
    const float* b = (const float*)d_in[1];
    const float* x  = a;
    const float* nm = b;
    if (n_in >= 2 && in_sizes[0] < in_sizes[1]) { x = b; nm = a; }
    float* out = (float*)d_out;
    (void)out_size;

    // Idempotent; called unconditionally (no static guards per harness rules).
    cudaFuncSetAttribute(noise_model_kernel,
                         cudaFuncAttributeMaxDynamicSharedMemorySize,
                         SMEM_TOTAL);

    noise_model_kernel<<<296, 1024, SMEM_TOTAL>>>((const float4*)x, nm, (float4*)out);
}